// round 13
// baseline (speedup 1.0000x reference)
#include <cuda_runtime.h>
#include <cuda_bf16.h>

// PositionEmbeddingSine: out[p, d*64 + 2k + {0,1}] = {sin, cos}(c_d * sc_d * 10000^(-k/32))
// sc_d = 2*pi / (s_d - 1 + eps); scatter row == point index p (b = repeat(arange, max_len)).
//
// Coordinates are integers in [0,128), so only 3*128*32 = 12288 distinct
// (sin,cos) pairs exist. Kernel A tabulates them (96 KB); kernel B streams
// the 252 MB output with zero transcendentals: LDG coords + LDS.128 table
// + STG.128 .cs. Discriminates MUFU-vs-DRAM bound.

#define SCALE_2PI 6.283185307179586f
#define EPS_F 1e-6f
#define LOG2_TEMP 13.287712379549449f   // log2(10000)

#define TAB_C 128
#define TAB_K 32
#define TAB_ENTRIES (3 * TAB_C * TAB_K)          // 12288 float2 = 96 KB
#define TAB_BYTES (TAB_ENTRIES * 8)

__device__ float2 g_tab[TAB_ENTRIES];            // [d][c][k]

// Kernel A: build the table. 48 blocks x 256 threads = 12288 entries.
__global__ void build_table_kernel(const int* __restrict__ sx_p,
                                   const int* __restrict__ sy_p,
                                   const int* __restrict__ sz_p)
{
    int idx = blockIdx.x * blockDim.x + threadIdx.x;
    if (idx >= TAB_ENTRIES) return;
    int d = idx / (TAB_C * TAB_K);
    int c = (idx / TAB_K) % TAB_C;
    int k = idx % TAB_K;

    int s = (d == 0) ? *sx_p : (d == 1) ? *sy_p : *sz_p;
    float sc = SCALE_2PI / ((float)(s - 1) + EPS_F);
    float invt = exp2f(-(float)k * (LOG2_TEMP / 32.0f));

    float2 v;
    __sincosf((float)c * sc * invt, &v.x, &v.y);
    g_tab[idx] = v;
}

// Kernel B: persistent grid-stride streamer. 16 lanes per point; lane r
// emits pairs k=2r,2r+1 for all 3 dims: 3 LDS.128 + 3 STG.128 per point.
__global__ __launch_bounds__(256) void pe_sine_kernel(
    const int4* __restrict__ coords4,
    const int* __restrict__ sx_p,
    const int* __restrict__ sy_p,
    const int* __restrict__ sz_p,
    float* __restrict__ out,
    int M)
{
    extern __shared__ float4 tab4[];             // 6144 float4 = 96 KB

    // Stage table GMEM -> SMEM (L2-resident after first block).
    const float4* gt4 = (const float4*)g_tab;
    for (int i = threadIdx.x; i < TAB_BYTES / 16; i += 256)
        tab4[i] = gt4[i];
    __syncthreads();

    int tid = threadIdx.x;
    int r = tid & 15;
    // lane r reads table[d][c][2r..2r+1] = one float4 at (d*128 + c)*16 + r
    const float4* tab_base = tab4 + r;

    int stride = gridDim.x * 16;
    for (int p = blockIdx.x * 16 + (tid >> 4); p < M; p += stride) {
        int4 c = __ldg(&coords4[p]);
        float* base = out + (long long)p * 192LL + 4 * r;

        unsigned cx = (unsigned)c.y, cy = (unsigned)c.z, cz = (unsigned)c.w;
        if ((cx | cy | cz) < TAB_C) {
            // hot path: pure table lookups
            __stcs((float4*)(base),       tab_base[(0 * TAB_C + cx) * 16]);
            __stcs((float4*)(base +  64), tab_base[(1 * TAB_C + cy) * 16]);
            __stcs((float4*)(base + 128), tab_base[(2 * TAB_C + cz) * 16]);
        } else {
            // safety fallback for out-of-table coords (never taken for this dataset)
            float s0 = SCALE_2PI / ((float)(*sx_p - 1) + EPS_F);
            float s1 = SCALE_2PI / ((float)(*sy_p - 1) + EPS_F);
            float s2 = SCALE_2PI / ((float)(*sz_p - 1) + EPS_F);
            float t0 = exp2f(-(float)(2 * r) * (LOG2_TEMP / 32.0f));
            float t1 = exp2f(-(float)(2 * r + 1) * (LOG2_TEMP / 32.0f));
            float v0 = (float)c.y * s0, v1 = (float)c.z * s1, v2 = (float)c.w * s2;
            float4 o0, o1, o2;
            __sincosf(v0 * t0, &o0.x, &o0.y); __sincosf(v0 * t1, &o0.z, &o0.w);
            __sincosf(v1 * t0, &o1.x, &o1.y); __sincosf(v1 * t1, &o1.z, &o1.w);
            __sincosf(v2 * t0, &o2.x, &o2.y); __sincosf(v2 * t1, &o2.z, &o2.w);
            __stcs((float4*)(base), o0);
            __stcs((float4*)(base + 64), o1);
            __stcs((float4*)(base + 128), o2);
        }
    }
}

extern "C" void kernel_launch(void* const* d_in, const int* in_sizes, int n_in,
                              void* d_out, int out_size) {
    const int* coords = (const int*)d_in[0];
    const int* sx_p   = (const int*)d_in[1];
    const int* sy_p   = (const int*)d_in[2];
    const int* sz_p   = (const int*)d_in[3];
    float* out = (float*)d_out;

    int M = in_sizes[0] / 4;

    static int smem_set = 0;
    if (!smem_set) {
        cudaFuncSetAttribute(pe_sine_kernel,
                             cudaFuncAttributeMaxDynamicSharedMemorySize,
                             TAB_BYTES);
        smem_set = 1;
    }

    build_table_kernel<<<(TAB_ENTRIES + 255) / 256, 256>>>(sx_p, sy_p, sz_p);

    int blocks = 2 * 148;   // ~2 CTAs/SM, grid-stride covers all points
    pe_sine_kernel<<<blocks, 256, TAB_BYTES>>>((const int4*)coords,
                                               sx_p, sy_p, sz_p, out, M);
}

// round 14
// speedup vs baseline: 1.0526x; 1.0526x over previous
#include <cuda_runtime.h>
#include <cuda_bf16.h>

// PositionEmbeddingSine: out[p, d*64 + 2k + {0,1}] = {sin, cos}(c_d * sc_d * 10000^(-k/32))
// sc_d = 2*pi / (s_d - 1 + eps); scatter row == point index p
// (b = repeat(arange(n_batches), max_len) -> identity scatter).
//
// sx == sy == sz == 128 here, so ONE 32 KB (sin,cos) table [c][k] serves all
// 3 dims. Each persistent CTA builds it in smem (amortized), then streams the
// 252 MB output with 1 LDG + 3 LDS.128 + 3 STG.128 per thread-iter - no MUFU.
// 32 KB smem keeps ~6 CTAs/SM resident (unlike the 96 KB version, occ 24%).
// Fallback compute path handles unequal/large spatial dims (never taken here).

#define SCALE_2PI 6.283185307179586f
#define EPS_F 1e-6f
#define LOG2_TEMP 13.287712379549449f   // log2(10000)

#define TAB_C 128
#define TAB_K 32

__global__ __launch_bounds__(256) void pe_sine_kernel(
    const int4* __restrict__ coords4,
    const int* __restrict__ sx_p,
    const int* __restrict__ sy_p,
    const int* __restrict__ sz_p,
    float* __restrict__ out,
    int M)
{
    __shared__ float2 tab2[TAB_C * TAB_K];   // 32 KB: (sin,cos)[c][k]
    __shared__ float s_sc[3];
    __shared__ int s_flag;

    int tid = threadIdx.x;
    int sx = __ldg(sx_p), sy = __ldg(sy_p), sz = __ldg(sz_p);
    if (tid == 0)
        s_flag = (sx == sy) && (sy == sz) && (sx <= TAB_C);
    if (tid < 3) {
        int s = (tid == 0) ? sx : (tid == 1) ? sy : sz;
        s_sc[tid] = SCALE_2PI / ((float)(s - 1) + EPS_F);
    }

    // Build the shared table (valid when all dims equal; built from sx).
    float sc0 = SCALE_2PI / ((float)(sx - 1) + EPS_F);
#pragma unroll
    for (int i = 0; i < (TAB_C * TAB_K) / 256; i++) {
        int idx = tid + i * 256;
        int c = idx >> 5;       // / TAB_K
        int k = idx & 31;       // % TAB_K
        float invt = exp2f(-(float)k * (LOG2_TEMP / 32.0f));
        float2 v;
        __sincosf((float)c * sc0 * invt, &v.x, &v.y);
        tab2[idx] = v;
    }
    __syncthreads();

    int r = tid & 15;
    // lane r reads (sin,cos) pairs k=2r,2r+1 for coord c: float4 at c*16 + r
    const float4* tabf4 = ((const float4*)tab2) + r;
    bool use_tab = (s_flag != 0);
    float s0 = s_sc[0], s1 = s_sc[1], s2 = s_sc[2];
    float t0 = exp2f(-(float)(2 * r) * (LOG2_TEMP / 32.0f));
    float t1 = exp2f(-(float)(2 * r + 1) * (LOG2_TEMP / 32.0f));

    int stride = gridDim.x * 16;
    for (int p = blockIdx.x * 16 + (tid >> 4); p < M; p += stride) {
        int4 c = __ldg(&coords4[p]);
        float* base = out + (long long)p * 192LL + 4 * r;
        unsigned cx = (unsigned)c.y, cy = (unsigned)c.z, cz = (unsigned)c.w;

        if (use_tab && ((cx | cy | cz) < (unsigned)TAB_C)) {
            // hot path: pure conflict-free table lookups, zero MUFU
            __stcs((float4*)(base),       tabf4[cx * 16]);
            __stcs((float4*)(base +  64), tabf4[cy * 16]);
            __stcs((float4*)(base + 128), tabf4[cz * 16]);
        } else {
            // general fallback (never taken for this dataset)
            float v0 = (float)c.y * s0, v1 = (float)c.z * s1, v2 = (float)c.w * s2;
            float4 o0, o1, o2;
            __sincosf(v0 * t0, &o0.x, &o0.y); __sincosf(v0 * t1, &o0.z, &o0.w);
            __sincosf(v1 * t0, &o1.x, &o1.y); __sincosf(v1 * t1, &o1.z, &o1.w);
            __sincosf(v2 * t0, &o2.x, &o2.y); __sincosf(v2 * t1, &o2.z, &o2.w);
            __stcs((float4*)(base),       o0);
            __stcs((float4*)(base +  64), o1);
            __stcs((float4*)(base + 128), o2);
        }
    }
}

extern "C" void kernel_launch(void* const* d_in, const int* in_sizes, int n_in,
                              void* d_out, int out_size) {
    const int* coords = (const int*)d_in[0];
    const int* sx_p   = (const int*)d_in[1];
    const int* sy_p   = (const int*)d_in[2];
    const int* sz_p   = (const int*)d_in[3];
    float* out = (float*)d_out;

    int M = in_sizes[0] / 4;

    // Persistent grid: ~6 CTAs/SM (32 KB smem each), grid-stride over points.
    int blocks = 6 * 148;
    pe_sine_kernel<<<blocks, 256>>>((const int4*)coords, sx_p, sy_p, sz_p,
                                    out, M);
}